// round 14
// baseline (speedup 1.0000x reference)
#include <cuda_runtime.h>

#define NW 6
#define NL 4
#define HP 112
#define WP 112
#define NB 8
#define OC 16
#define NPIX (NB*HP*WP)

__device__ float g_H[NB*OC*HP*224];   // horizontally-upsampled y

// ---------------------------------------------------------------------------
// Fused pixels kernel. PROLOGUE (per block, redundant): circuit sim ->
// M_w -> 27-term trig table sT. MAIN: two adjacent patch pixels per thread
// (224 active threads = 4 full patch rows of 56 pairs = 7 exact warps), then
// HORIZONTAL upsample blend in-register (neighbors via shfl + per-warp smem
// boundary values) -> H (float4 per channel).
// ---------------------------------------------------------------------------
__global__ void __launch_bounds__(256)
k_pixels(const float* __restrict__ x,
         const float* __restrict__ w,
         const float* __restrict__ fcw,
         const float* __restrict__ fcb,
         const float* __restrict__ lng,
         const float* __restrict__ lnb)
{
    __shared__ float2 sU[24][4];
    __shared__ float2 phi[8][65];
    __shared__ float  sD[4][64][13];
    __shared__ float  Mre[6][8][8];
    __shared__ float  Mim[6][8][8];
    __shared__ float  sT[162], sFC[96], sFB[16], sG[16], sB[16];
    __shared__ float  sLy[7][16];   // lane31's vout.y per warp/channel
    __shared__ float  sRx[7][16];   // lane0's  vout.x per warp/channel

    const int tid  = threadIdx.x;          // 256 threads = 8 warps
    const int wrp  = tid >> 5;
    const int lane = tid & 31;
    const unsigned FULL = 0xFFFFFFFFu;

    if (tid < 96)  sFC[tid] = fcw[tid];
    if (tid >= 96  && tid < 112) sFB[tid - 96]  = fcb[tid - 96];
    if (tid >= 112 && tid < 128) sG [tid - 112] = lng[tid - 112];
    if (tid >= 128 && tid < 144) sB [tid - 128] = lnb[tid - 128];

    if (tid >= 160 && tid < 184) {
        const int gi = tid - 160;
        const float ph = w[gi*3 + 0];
        const float th = w[gi*3 + 1];
        const float om = w[gi*3 + 2];
        const float ch = cosf(0.5f * th), sh = sinf(0.5f * th);
        float cp, sp, cm, sm;
        sincosf(-0.5f * (ph + om), &sp, &cp);
        sincosf(-0.5f * (ph - om), &sm, &cm);
        sU[gi][0] = make_float2( cp*ch,  sp*ch);
        sU[gi][1] = make_float2(-cm*sh,  sm*sh);
        sU[gi][2] = make_float2( cm*sh,  sm*sh);
        sU[gi][3] = make_float2( cp*ch, -sp*ch);
    }
    __syncthreads();

    // ---- circuit: warp wrp simulates basis state |wrp>|000> ----
    {
        float ar = (lane == wrp * 8) ? 1.f : 0.f, ai = 0.f;
        float br = (lane + 32 == wrp * 8) ? 1.f : 0.f, bi = 0.f;

        for (int l = 0; l < NL; l++) {
            #pragma unroll
            for (int q = 0; q < NW; q++) {
                const float2 u00 = sU[l*6+q][0], u01 = sU[l*6+q][1];
                const float2 u10 = sU[l*6+q][2], u11 = sU[l*6+q][3];
                if (q == 0) {
                    const float nar = u00.x*ar - u00.y*ai + u01.x*br - u01.y*bi;
                    const float nai = u00.x*ai + u00.y*ar + u01.x*bi + u01.y*br;
                    const float nbr = u10.x*ar - u10.y*ai + u11.x*br - u11.y*bi;
                    const float nbi = u10.x*ai + u10.y*ar + u11.x*bi + u11.y*br;
                    ar = nar; ai = nai; br = nbr; bi = nbi;
                } else {
                    const int stride = 1 << (5 - q);
                    const float par = __shfl_xor_sync(FULL, ar, stride);
                    const float pai = __shfl_xor_sync(FULL, ai, stride);
                    const float pbr = __shfl_xor_sync(FULL, br, stride);
                    const float pbi = __shfl_xor_sync(FULL, bi, stride);
                    const bool hi = (lane & stride) != 0;
                    const float2 A  = hi ? u11 : u00;
                    const float2 Bc = hi ? u10 : u01;
                    {
                        const float nr = A.x*ar - A.y*ai + Bc.x*par - Bc.y*pai;
                        const float ni = A.x*ai + A.y*ar + Bc.x*pai + Bc.y*par;
                        ar = nr; ai = ni;
                    }
                    {
                        const float nr = A.x*br - A.y*bi + Bc.x*pbr - Bc.y*pbi;
                        const float ni = A.x*bi + A.y*br + Bc.x*pbi + Bc.y*pbr;
                        br = nr; bi = ni;
                    }
                }
            }
            const int r = l % (NW - 1) + 1;
            int i0 = lane, i1 = lane + 32;
            #pragma unroll
            for (int q = NW - 1; q >= 0; q--) {
                const int cpos = 5 - q;
                const int tpos = 5 - ((q + r) % NW);
                i0 ^= ((i0 >> cpos) & 1) << tpos;
                i1 ^= ((i1 >> cpos) & 1) << tpos;
            }
            const float g0ar = __shfl_sync(FULL, ar, i0 & 31);
            const float g0ai = __shfl_sync(FULL, ai, i0 & 31);
            const float g0br = __shfl_sync(FULL, br, i0 & 31);
            const float g0bi = __shfl_sync(FULL, bi, i0 & 31);
            const float g1ar = __shfl_sync(FULL, ar, i1 & 31);
            const float g1ai = __shfl_sync(FULL, ai, i1 & 31);
            const float g1br = __shfl_sync(FULL, br, i1 & 31);
            const float g1bi = __shfl_sync(FULL, bi, i1 & 31);
            ar = (i0 < 32) ? g0ar : g0br;
            ai = (i0 < 32) ? g0ai : g0bi;
            br = (i1 < 32) ? g1ar : g1br;
            bi = (i1 < 32) ? g1ai : g1bi;
        }
        phi[wrp][lane]      = make_float2(ar, ai);
        phi[wrp][lane + 32] = make_float2(br, bi);
    }
    __syncthreads();

    // ---- Phase D1: pair = tid&63 (fast), chunk = tid>>6 (slow) ----
    {
        const int pair = tid & 63, chunk = tid >> 6;
        const int i = pair >> 3, jj = pair & 7;
        const float s0 = (chunk & 2) ? -1.f : 1.f;
        const float s1 = (chunk & 1) ? -1.f : 1.f;
        float acc[12];
        #pragma unroll
        for (int m = 0; m < 12; m++) acc[m] = 0.f;
        #pragma unroll
        for (int k = 0; k < 16; k++) {
            const int t = chunk * 16 + k;
            const float2 a = phi[i][t], bb = phi[jj][t];
            const float pre = a.x*bb.x + a.y*bb.y;
            const float pim = a.x*bb.y - a.y*bb.x;
            acc[0]  += pre;  acc[1]  += pim;
            acc[2]  += pre;  acc[3]  += pim;
            if (k & 8) { acc[4] -= pre; acc[5] -= pim; } else { acc[4] += pre; acc[5] += pim; }
            if (k & 4) { acc[6] -= pre; acc[7] -= pim; } else { acc[6] += pre; acc[7] += pim; }
            if (k & 2) { acc[8] -= pre; acc[9] -= pim; } else { acc[8] += pre; acc[9] += pim; }
            if (k & 1) { acc[10] -= pre; acc[11] -= pim; } else { acc[10] += pre; acc[11] += pim; }
        }
        acc[0] *= s0; acc[1] *= s0;
        acc[2] *= s1; acc[3] *= s1;
        #pragma unroll
        for (int m = 0; m < 12; m++) sD[chunk][pair][m] = acc[m];
    }
    __syncthreads();

    // ---- Phase D2: reduce 4 chunks -> Mre/Mim ----
    for (int o = tid; o < 768; o += 256) {
        const int c = o & 1, pair = (o >> 1) & 63, q = o >> 7;
        const float s = sD[0][pair][2*q+c] + sD[1][pair][2*q+c]
                      + sD[2][pair][2*q+c] + sD[3][pair][2*q+c];
        const int i = pair >> 3, jj = pair & 7;
        if (c) Mim[q][i][jj] = s; else Mre[q][i][jj] = s;
    }
    __syncthreads();

    // ---- Phase E: 8 contributing (i,jj) pairs per term -> sT ----
    if (tid < 6 * 27) {
        const int q = tid / 27, term = tid % 27;
        const int tt[3] = { term / 9, (term / 3) % 3, term % 3 };
        float acc = 0.f;
        #pragma unroll
        for (int k = 0; k < 8; k++) {
            int i = 0, jj = 0;
            float sgn = 0.125f;
            #pragma unroll
            for (int c = 0; c < 3; c++) {
                const int sel = (k >> c) & 1;
                const int t = tt[c];
                int bi, bj;
                if (t == 2) { bi = sel ^ 1; bj = sel; }
                else {
                    bi = sel; bj = sel;
                    if (t == 1 && sel == 1) sgn = -sgn;
                }
                i  |= bi << (2 - c);
                jj |= bj << (2 - c);
            }
            const int kph = (__popc(i) - __popc(jj)) & 3;
            const float mre = Mre[q][i][jj], mim = Mim[q][i][jj];
            const float f = (kph == 0) ? mre : (kph == 1) ? -mim
                          : (kph == 2) ? -mre : mim;
            acc += sgn * f;
        }
        sT[tid] = acc;
    }
    __syncthreads();

    // ========= MAIN: 224 active threads = 4 full rows of 56 pairs =========
    const bool active = tid < 224;
    float2 vout[OC];
    int b = 0, hp = 0, wpp = 0;

    if (active) {
        const int gr = blockIdx.x * 4 + tid / 56;   // global patch row 0..895
        b   = gr / HP;
        hp  = gr % HP;
        wpp = tid % 56;                              // pair index in row

        float g0[3][3], g1[3][3];
        #pragma unroll
        for (int c = 0; c < 3; c++) {
            const float* base = x + (((long)(b * 3 + c) * 224 + 2 * hp) * 224 + 4 * wpp);
            const float4 r0 = *reinterpret_cast<const float4*>(base);
            const float4 r1 = *reinterpret_cast<const float4*>(base + 224);
            const float a0 = 0.25f * (r0.x + r0.y + r1.x + r1.y);
            const float a1 = 0.25f * (r0.z + r0.w + r1.z + r1.w);
            float sn, cs;
            __sincosf(a0, &sn, &cs);
            g0[c][0] = 1.f; g0[c][1] = cs; g0[c][2] = sn;
            __sincosf(a1, &sn, &cs);
            g1[c][0] = 1.f; g1[c][1] = cs; g1[c][2] = sn;
        }

        #pragma unroll
        for (int half = 0; half < 2; half++) {
            float (*gg)[3] = half ? g1 : g0;

            float e[6];
            #pragma unroll
            for (int q = 0; q < 6; q++) e[q] = 0.f;
            #pragma unroll
            for (int t0 = 0; t0 < 3; t0++)
                #pragma unroll
                for (int t1 = 0; t1 < 3; t1++) {
                    const float p01 = gg[0][t0] * gg[1][t1];
                    #pragma unroll
                    for (int t2 = 0; t2 < 3; t2++) {
                        const float bas = p01 * gg[2][t2];
                        const int t = (t0 * 3 + t1) * 3 + t2;
                        #pragma unroll
                        for (int q = 0; q < 6; q++) e[q] += sT[q * 27 + t] * bas;
                    }
                }

            float y[OC], mu = 0.f;
            #pragma unroll
            for (int o = 0; o < OC; o++) {
                float acc = sFB[o];
                #pragma unroll
                for (int q = 0; q < 6; q++) acc += sFC[o * 6 + q] * e[q];
                y[o] = acc;
                mu += acc;
            }
            mu *= (1.f / OC);
            float var = 0.f;
            #pragma unroll
            for (int o = 0; o < OC; o++) { const float d = y[o] - mu; var += d * d; }
            var *= (1.f / OC);
            const float inv = rsqrtf(var + 1e-5f);
            #pragma unroll
            for (int o = 0; o < OC; o++) {
                const float v = fmaxf((y[o] - mu) * inv * sG[o] + sB[o], 0.f);
                if (half) vout[o].y = v; else vout[o].x = v;
            }
        }

        // stage per-warp boundary values for horizontal neighbors
        if (lane == 31) {
            #pragma unroll
            for (int o = 0; o < OC; o++) sLy[wrp][o] = vout[o].y;
        }
        if (lane == 0) {
            #pragma unroll
            for (int o = 0; o < OC; o++) sRx[wrp][o] = vout[o].x;
        }
    }
    __syncthreads();

    if (active) {
        // horizontal 2x blend -> H (4 output cols per channel, one STG.128)
        float* hb = &g_H[(((long)b * OC) * HP + hp) * 224 + 4 * wpp];
        #pragma unroll
        for (int o = 0; o < OC; o++) {
            const float vx = vout[o].x, vy = vout[o].y;
            const float sl = __shfl_up_sync(FULL, vy, 1);
            const float sr = __shfl_down_sync(FULL, vx, 1);
            float yl = sl;
            if (lane == 0 && wrp > 0) yl = sLy[wrp - 1][o];
            if (wpp == 0)             yl = vx;                  // left edge clamp
            float yr = sr;
            if (lane == 31 && wrp < 6) yr = sRx[wrp + 1][o];
            if (wpp == 55)             yr = vy;                 // right edge clamp
            const float4 h = make_float4(
                0.25f * yl + 0.75f * vx,
                0.75f * vx + 0.25f * vy,
                0.25f * vx + 0.75f * vy,
                0.75f * vy + 0.25f * yr);
            *reinterpret_cast<float4*>(hb + (long)o * HP * 224) = h;
        }
    }
}

// ---------------------------------------------------------------------------
// Kernel 2 (v6): VERTICAL-only 2x blend from H. One thread = 2 output rows
// x 8 cols: 6 LDG.128 + 32 FMA + 4 STG.128 for 16 outputs. Row clamp only.
// out[2m] = 0.25*H[m-1] + 0.75*H[m]; out[2m+1] = 0.75*H[m] + 0.25*H[m+1].
// ---------------------------------------------------------------------------
__global__ void __launch_bounds__(224)
k_resize(float* __restrict__ out)
{
    const int c8 = threadIdx.x;                       // 0..27 (8-col groups)
    const int m  = blockIdx.x * 8 + threadIdx.y;      // input row 0..111
    const int pl = blockIdx.y;                        // (b, oc) plane
    const float* Hb = g_H + (long)pl * HP * 224;

    const int rm = max(m - 1, 0), rp = min(m + 1, HP - 1);
    const float4* arow = reinterpret_cast<const float4*>(Hb + rm * 224 + 8 * c8);
    const float4* brow = reinterpret_cast<const float4*>(Hb + m  * 224 + 8 * c8);
    const float4* crow = reinterpret_cast<const float4*>(Hb + rp * 224 + 8 * c8);
    const float4 a0 = arow[0], a1 = arow[1];
    const float4 b0 = brow[0], b1 = brow[1];
    const float4 c0 = crow[0], c1 = crow[1];

    float* obase = out + (((long)pl * 224 + 2 * m) * 224 + 8 * c8);
    *reinterpret_cast<float4*>(obase) = make_float4(
        0.25f * a0.x + 0.75f * b0.x, 0.25f * a0.y + 0.75f * b0.y,
        0.25f * a0.z + 0.75f * b0.z, 0.25f * a0.w + 0.75f * b0.w);
    *reinterpret_cast<float4*>(obase + 4) = make_float4(
        0.25f * a1.x + 0.75f * b1.x, 0.25f * a1.y + 0.75f * b1.y,
        0.25f * a1.z + 0.75f * b1.z, 0.25f * a1.w + 0.75f * b1.w);
    *reinterpret_cast<float4*>(obase + 224) = make_float4(
        0.75f * b0.x + 0.25f * c0.x, 0.75f * b0.y + 0.25f * c0.y,
        0.75f * b0.z + 0.25f * c0.z, 0.75f * b0.w + 0.25f * c0.w);
    *reinterpret_cast<float4*>(obase + 228) = make_float4(
        0.75f * b1.x + 0.25f * c1.x, 0.75f * b1.y + 0.25f * c1.y,
        0.75f * b1.z + 0.25f * c1.z, 0.75f * b1.w + 0.25f * c1.w);
}

extern "C" void kernel_launch(void* const* d_in, const int* in_sizes, int n_in,
                              void* d_out, int out_size)
{
    const float* x   = (const float*)d_in[0];
    const float* wts = (const float*)d_in[1];
    const float* fcw = (const float*)d_in[2];
    const float* fcb = (const float*)d_in[3];
    const float* lng = (const float*)d_in[4];
    const float* lnb = (const float*)d_in[5];
    float* out = (float*)d_out;

    k_pixels<<<224, 256>>>(x, wts, fcw, fcb, lng, lnb);
    dim3 rb(28, 8);
    dim3 rg(HP / 8, NB * OC);
    k_resize<<<rg, rb>>>(out);
}

// round 15
// speedup vs baseline: 1.2137x; 1.2137x over previous
#include <cuda_runtime.h>

#define NW 6
#define NL 4
#define HP 112
#define WP 112
#define NB 8
#define OC 16
#define NPIX (NB*HP*WP)

__device__ float g_y[NB*OC*HP*WP];

// ---------------------------------------------------------------------------
// Fused pixels kernel (exact R10 version). PROLOGUE (per block, redundant,
// parallel): circuit sim (8 warps, register amplitudes + shuffles) -> M_w ->
// 27-term trig table sT. MAIN: two adjacent patch pixels per thread.
// ---------------------------------------------------------------------------
__global__ void __launch_bounds__(256)
k_pixels(const float* __restrict__ x,
         const float* __restrict__ w,
         const float* __restrict__ fcw,
         const float* __restrict__ fcb,
         const float* __restrict__ lng,
         const float* __restrict__ lnb)
{
    __shared__ float2 sU[24][4];
    __shared__ float2 phi[8][65];
    __shared__ float  sD[4][64][13];
    __shared__ float  Mre[6][8][8];
    __shared__ float  Mim[6][8][8];
    __shared__ float  sT[162], sFC[96], sFB[16], sG[16], sB[16];

    const int tid  = threadIdx.x;          // 256 threads = 8 warps
    const int wrp  = tid >> 5;
    const int lane = tid & 31;
    const unsigned FULL = 0xFFFFFFFFu;

    if (tid < 96)  sFC[tid] = fcw[tid];
    if (tid >= 96  && tid < 112) sFB[tid - 96]  = fcb[tid - 96];
    if (tid >= 112 && tid < 128) sG [tid - 112] = lng[tid - 112];
    if (tid >= 128 && tid < 144) sB [tid - 128] = lnb[tid - 128];

    if (tid >= 160 && tid < 184) {
        const int gi = tid - 160;
        const float ph = w[gi*3 + 0];
        const float th = w[gi*3 + 1];
        const float om = w[gi*3 + 2];
        const float ch = cosf(0.5f * th), sh = sinf(0.5f * th);
        float cp, sp, cm, sm;
        sincosf(-0.5f * (ph + om), &sp, &cp);
        sincosf(-0.5f * (ph - om), &sm, &cm);
        sU[gi][0] = make_float2( cp*ch,  sp*ch);
        sU[gi][1] = make_float2(-cm*sh,  sm*sh);
        sU[gi][2] = make_float2( cm*sh,  sm*sh);
        sU[gi][3] = make_float2( cp*ch, -sp*ch);
    }
    __syncthreads();

    // ---- circuit: warp wrp simulates basis state |wrp>|000> ----
    {
        float ar = (lane == wrp * 8) ? 1.f : 0.f, ai = 0.f;
        float br = (lane + 32 == wrp * 8) ? 1.f : 0.f, bi = 0.f;

        for (int l = 0; l < NL; l++) {
            #pragma unroll
            for (int q = 0; q < NW; q++) {
                const float2 u00 = sU[l*6+q][0], u01 = sU[l*6+q][1];
                const float2 u10 = sU[l*6+q][2], u11 = sU[l*6+q][3];
                if (q == 0) {
                    const float nar = u00.x*ar - u00.y*ai + u01.x*br - u01.y*bi;
                    const float nai = u00.x*ai + u00.y*ar + u01.x*bi + u01.y*br;
                    const float nbr = u10.x*ar - u10.y*ai + u11.x*br - u11.y*bi;
                    const float nbi = u10.x*ai + u10.y*ar + u11.x*bi + u11.y*br;
                    ar = nar; ai = nai; br = nbr; bi = nbi;
                } else {
                    const int stride = 1 << (5 - q);
                    const float par = __shfl_xor_sync(FULL, ar, stride);
                    const float pai = __shfl_xor_sync(FULL, ai, stride);
                    const float pbr = __shfl_xor_sync(FULL, br, stride);
                    const float pbi = __shfl_xor_sync(FULL, bi, stride);
                    const bool hi = (lane & stride) != 0;
                    const float2 A  = hi ? u11 : u00;
                    const float2 Bc = hi ? u10 : u01;
                    {
                        const float nr = A.x*ar - A.y*ai + Bc.x*par - Bc.y*pai;
                        const float ni = A.x*ai + A.y*ar + Bc.x*pai + Bc.y*par;
                        ar = nr; ai = ni;
                    }
                    {
                        const float nr = A.x*br - A.y*bi + Bc.x*pbr - Bc.y*pbi;
                        const float ni = A.x*bi + A.y*br + Bc.x*pbi + Bc.y*pbr;
                        br = nr; bi = ni;
                    }
                }
            }
            const int r = l % (NW - 1) + 1;
            int i0 = lane, i1 = lane + 32;
            #pragma unroll
            for (int q = NW - 1; q >= 0; q--) {
                const int cpos = 5 - q;
                const int tpos = 5 - ((q + r) % NW);
                i0 ^= ((i0 >> cpos) & 1) << tpos;
                i1 ^= ((i1 >> cpos) & 1) << tpos;
            }
            const float g0ar = __shfl_sync(FULL, ar, i0 & 31);
            const float g0ai = __shfl_sync(FULL, ai, i0 & 31);
            const float g0br = __shfl_sync(FULL, br, i0 & 31);
            const float g0bi = __shfl_sync(FULL, bi, i0 & 31);
            const float g1ar = __shfl_sync(FULL, ar, i1 & 31);
            const float g1ai = __shfl_sync(FULL, ai, i1 & 31);
            const float g1br = __shfl_sync(FULL, br, i1 & 31);
            const float g1bi = __shfl_sync(FULL, bi, i1 & 31);
            ar = (i0 < 32) ? g0ar : g0br;
            ai = (i0 < 32) ? g0ai : g0bi;
            br = (i1 < 32) ? g1ar : g1br;
            bi = (i1 < 32) ? g1ai : g1bi;
        }
        phi[wrp][lane]      = make_float2(ar, ai);
        phi[wrp][lane + 32] = make_float2(br, bi);
    }
    __syncthreads();

    // ---- Phase D1: pair = tid&63 (fast), chunk = tid>>6 (slow) ----
    {
        const int pair = tid & 63, chunk = tid >> 6;
        const int i = pair >> 3, jj = pair & 7;
        const float s0 = (chunk & 2) ? -1.f : 1.f;
        const float s1 = (chunk & 1) ? -1.f : 1.f;
        float acc[12];
        #pragma unroll
        for (int m = 0; m < 12; m++) acc[m] = 0.f;
        #pragma unroll
        for (int k = 0; k < 16; k++) {
            const int t = chunk * 16 + k;
            const float2 a = phi[i][t], bb = phi[jj][t];
            const float pre = a.x*bb.x + a.y*bb.y;
            const float pim = a.x*bb.y - a.y*bb.x;
            acc[0]  += pre;  acc[1]  += pim;
            acc[2]  += pre;  acc[3]  += pim;
            if (k & 8) { acc[4] -= pre; acc[5] -= pim; } else { acc[4] += pre; acc[5] += pim; }
            if (k & 4) { acc[6] -= pre; acc[7] -= pim; } else { acc[6] += pre; acc[7] += pim; }
            if (k & 2) { acc[8] -= pre; acc[9] -= pim; } else { acc[8] += pre; acc[9] += pim; }
            if (k & 1) { acc[10] -= pre; acc[11] -= pim; } else { acc[10] += pre; acc[11] += pim; }
        }
        acc[0] *= s0; acc[1] *= s0;
        acc[2] *= s1; acc[3] *= s1;
        #pragma unroll
        for (int m = 0; m < 12; m++) sD[chunk][pair][m] = acc[m];
    }
    __syncthreads();

    // ---- Phase D2: reduce 4 chunks -> Mre/Mim ----
    for (int o = tid; o < 768; o += 256) {
        const int c = o & 1, pair = (o >> 1) & 63, q = o >> 7;
        const float s = sD[0][pair][2*q+c] + sD[1][pair][2*q+c]
                      + sD[2][pair][2*q+c] + sD[3][pair][2*q+c];
        const int i = pair >> 3, jj = pair & 7;
        if (c) Mim[q][i][jj] = s; else Mre[q][i][jj] = s;
    }
    __syncthreads();

    // ---- Phase E: 8 contributing (i,jj) pairs per term -> sT ----
    if (tid < 6 * 27) {
        const int q = tid / 27, term = tid % 27;
        const int tt[3] = { term / 9, (term / 3) % 3, term % 3 };
        float acc = 0.f;
        #pragma unroll
        for (int k = 0; k < 8; k++) {
            int i = 0, jj = 0;
            float sgn = 0.125f;
            #pragma unroll
            for (int c = 0; c < 3; c++) {
                const int sel = (k >> c) & 1;
                const int t = tt[c];
                int bi, bj;
                if (t == 2) { bi = sel ^ 1; bj = sel; }
                else {
                    bi = sel; bj = sel;
                    if (t == 1 && sel == 1) sgn = -sgn;
                }
                i  |= bi << (2 - c);
                jj |= bj << (2 - c);
            }
            const int kph = (__popc(i) - __popc(jj)) & 3;
            const float mre = Mre[q][i][jj], mim = Mim[q][i][jj];
            const float f = (kph == 0) ? mre : (kph == 1) ? -mim
                          : (kph == 2) ? -mre : mim;
            acc += sgn * f;
        }
        sT[tid] = acc;
    }
    __syncthreads();

    // ================== MAIN: two patch pixels per thread ==================
    const int pp = blockIdx.x * blockDim.x + tid;
    const int WPH = WP / 2;
    const int b   = pp / (HP * WPH);
    const int rem = pp % (HP * WPH);
    const int hp  = rem / WPH, wpp = rem % WPH;

    float g0[3][3], g1[3][3];
    #pragma unroll
    for (int c = 0; c < 3; c++) {
        const float* base = x + (((long)(b * 3 + c) * 224 + 2 * hp) * 224 + 4 * wpp);
        const float4 r0 = *reinterpret_cast<const float4*>(base);
        const float4 r1 = *reinterpret_cast<const float4*>(base + 224);
        const float a0 = 0.25f * (r0.x + r0.y + r1.x + r1.y);
        const float a1 = 0.25f * (r0.z + r0.w + r1.z + r1.w);
        float sn, cs;
        __sincosf(a0, &sn, &cs);
        g0[c][0] = 1.f; g0[c][1] = cs; g0[c][2] = sn;
        __sincosf(a1, &sn, &cs);
        g1[c][0] = 1.f; g1[c][1] = cs; g1[c][2] = sn;
    }

    float2 vout[OC];
    #pragma unroll
    for (int half = 0; half < 2; half++) {
        float (*gg)[3] = half ? g1 : g0;

        float e[6];
        #pragma unroll
        for (int q = 0; q < 6; q++) e[q] = 0.f;
        #pragma unroll
        for (int t0 = 0; t0 < 3; t0++)
            #pragma unroll
            for (int t1 = 0; t1 < 3; t1++) {
                const float p01 = gg[0][t0] * gg[1][t1];
                #pragma unroll
                for (int t2 = 0; t2 < 3; t2++) {
                    const float bas = p01 * gg[2][t2];
                    const int t = (t0 * 3 + t1) * 3 + t2;
                    #pragma unroll
                    for (int q = 0; q < 6; q++) e[q] += sT[q * 27 + t] * bas;
                }
            }

        float y[OC], mu = 0.f;
        #pragma unroll
        for (int o = 0; o < OC; o++) {
            float acc = sFB[o];
            #pragma unroll
            for (int q = 0; q < 6; q++) acc += sFC[o * 6 + q] * e[q];
            y[o] = acc;
            mu += acc;
        }
        mu *= (1.f / OC);
        float var = 0.f;
        #pragma unroll
        for (int o = 0; o < OC; o++) { const float d = y[o] - mu; var += d * d; }
        var *= (1.f / OC);
        const float inv = rsqrtf(var + 1e-5f);
        #pragma unroll
        for (int o = 0; o < OC; o++) {
            const float v = fmaxf((y[o] - mu) * inv * sG[o] + sB[o], 0.f);
            if (half) vout[o].y = v; else vout[o].x = v;
        }
    }

    #pragma unroll
    for (int o = 0; o < OC; o++) {
        *reinterpret_cast<float2*>(
            &g_y[(((long)b * OC + o) * HP + hp) * WP + 2 * wpp]) = vout[o];
    }
}

// ---------------------------------------------------------------------------
// Kernel 2 (v7): 2x bilinear upsample, 2-input-row mapping.
// Output rows 2m+1 and 2m+2 both blend the SAME y rows (m, m+1):
//   row 2m+1 = 0.75*y[m] + 0.25*y[m+1]; row 2m+2 = 0.25*y[m] + 0.75*y[m+1].
// Thread = (pl, m, c4): 6 LDG + 32 FMA + 2 STG.128 for 2x4 outputs.
// m == 111 handles the edge rows: out row 223 = hblend(y[111]) and
// out row 0 = hblend(y[0]) (weights (1,0)/(0,1), row B redirected to 0).
// ---------------------------------------------------------------------------
__global__ void __launch_bounds__(256)
k_resize(float* __restrict__ out)
{
    const int idx = blockIdx.x * 256 + threadIdx.x;   // 3136 blocks exactly
    const int c4 = idx % 56;                          // 4-col output group
    const int m  = (idx / 56) % HP;                   // input row (pair base)
    const int pl = idx / (56 * HP);                   // (b, oc) plane
    const float* yb = g_y + (long)pl * HP * WP;

    const bool last = (m == HP - 1);
    const int mb = last ? 0 : m + 1;                  // second input row
    const int c0 = 2 * c4;
    const int cm = max(c0 - 1, 0), c2 = min(c0 + 2, WP - 1);

    // horizontal blends for both input rows (4 output cols each)
    float hA[4], hB[4];
    {
        const float* rp = yb + m * WP;
        const float  vm1 = __ldg(rp + cm);
        const float2 v01 = *reinterpret_cast<const float2*>(rp + c0);
        const float  v2  = __ldg(rp + c2);
        hA[0] = 0.25f * vm1   + 0.75f * v01.x;
        hA[1] = 0.75f * v01.x + 0.25f * v01.y;
        hA[2] = 0.25f * v01.x + 0.75f * v01.y;
        hA[3] = 0.75f * v01.y + 0.25f * v2;
    }
    {
        const float* rp = yb + mb * WP;
        const float  vm1 = __ldg(rp + cm);
        const float2 v01 = *reinterpret_cast<const float2*>(rp + c0);
        const float  v2  = __ldg(rp + c2);
        hB[0] = 0.25f * vm1   + 0.75f * v01.x;
        hB[1] = 0.75f * v01.x + 0.25f * v01.y;
        hB[2] = 0.25f * v01.x + 0.75f * v01.y;
        hB[3] = 0.75f * v01.y + 0.25f * v2;
    }

    // vertical weights; edge thread writes rows 223 (pure A) and 0 (pure B)
    const float wTA = last ? 1.f : 0.75f, wTB = last ? 0.f : 0.25f;
    const float wBA = last ? 0.f : 0.25f, wBB = last ? 1.f : 0.75f;
    const int ohT = 2 * m + 1;
    const int ohB = last ? 0 : 2 * m + 2;

    float* ot = out + (((long)pl * 224 + ohT) * 224 + 4 * c4);
    float* ob = out + (((long)pl * 224 + ohB) * 224 + 4 * c4);
    *reinterpret_cast<float4*>(ot) = make_float4(
        wTA * hA[0] + wTB * hB[0], wTA * hA[1] + wTB * hB[1],
        wTA * hA[2] + wTB * hB[2], wTA * hA[3] + wTB * hB[3]);
    *reinterpret_cast<float4*>(ob) = make_float4(
        wBA * hA[0] + wBB * hB[0], wBA * hA[1] + wBB * hB[1],
        wBA * hA[2] + wBB * hB[2], wBA * hA[3] + wBB * hB[3]);
}

extern "C" void kernel_launch(void* const* d_in, const int* in_sizes, int n_in,
                              void* d_out, int out_size)
{
    const float* x   = (const float*)d_in[0];
    const float* wts = (const float*)d_in[1];
    const float* fcw = (const float*)d_in[2];
    const float* fcb = (const float*)d_in[3];
    const float* lng = (const float*)d_in[4];
    const float* lnb = (const float*)d_in[5];
    float* out = (float*)d_out;

    k_pixels<<<NPIX / 2 / 256, 256>>>(x, wts, fcw, fcb, lng, lnb);
    k_resize<<<(56 * HP * NB * OC) / 256, 256>>>(out);
}